// round 1
// baseline (speedup 1.0000x reference)
#include <cuda_runtime.h>
#include <math.h>

// Problem: N = 4096
//   yout = tanh(yin @ (w + alpha*hebb) + input)            [1, N]
//   hebb' = (1-eta)*hebb + eta * outer(yin, yout)          [N, N]
// Inputs (metadata order): input[N], yin[N], hebb[N*N], w[N*N], alpha[N*N], eta[1]
// Output: d_out = [ yout (N floats) | hebb_new (N*N floats) ]

#define N 4096
#define SPLITS 64            // row splits for the matvec (split-K)
#define ROWS_PER (N / SPLITS)  // 64 rows per split
#define MV_THREADS 256       // each thread owns 4 columns -> 1024 cols per block
#define COL_BLOCKS (N / (MV_THREADS * 4))  // 4

// Deterministic scratch for split-K partial sums (1 MB). No atomics ->
// bit-identical results every replay.
__device__ float g_partial[SPLITS * N];

// ---------------------------------------------------------------------------
// Kernel 1: partial matvec.
// block (x=col chunk, y=row split). Each thread accumulates 4 columns over
// ROWS_PER rows. All matrix loads are coalesced float4; yin[i] is a warp-
// uniform broadcast load.
// ---------------------------------------------------------------------------
__global__ void __launch_bounds__(MV_THREADS) k_matvec_partial(
    const float* __restrict__ yin,
    const float* __restrict__ w,
    const float* __restrict__ alpha,
    const float* __restrict__ hebb)
{
    const int j  = blockIdx.x * (MV_THREADS * 4) + threadIdx.x * 4;
    const int r0 = blockIdx.y * ROWS_PER;

    float4 acc = make_float4(0.f, 0.f, 0.f, 0.f);

    const float* __restrict__ wp = w     + (size_t)r0 * N + j;
    const float* __restrict__ ap = alpha + (size_t)r0 * N + j;
    const float* __restrict__ hp = hebb  + (size_t)r0 * N + j;

    #pragma unroll 4
    for (int i = 0; i < ROWS_PER; ++i) {
        const float y = __ldg(&yin[r0 + i]);
        const float4 w4 = *reinterpret_cast<const float4*>(wp);
        const float4 a4 = *reinterpret_cast<const float4*>(ap);
        const float4 h4 = *reinterpret_cast<const float4*>(hp);
        acc.x = fmaf(y, fmaf(a4.x, h4.x, w4.x), acc.x);
        acc.y = fmaf(y, fmaf(a4.y, h4.y, w4.y), acc.y);
        acc.z = fmaf(y, fmaf(a4.z, h4.z, w4.z), acc.z);
        acc.w = fmaf(y, fmaf(a4.w, h4.w, w4.w), acc.w);
        wp += N; ap += N; hp += N;
    }

    *reinterpret_cast<float4*>(&g_partial[(size_t)blockIdx.y * N + j]) = acc;
}

// ---------------------------------------------------------------------------
// Kernel 2: reduce the SPLITS partials, add input, tanh, write yout to
// d_out[0:N].
// ---------------------------------------------------------------------------
__global__ void k_reduce_tanh(const float* __restrict__ input,
                              float* __restrict__ out_yout)
{
    const int j = blockIdx.x * blockDim.x + threadIdx.x;
    if (j >= N) return;
    float s = 0.f;
    #pragma unroll 16
    for (int p = 0; p < SPLITS; ++p)
        s += g_partial[(size_t)p * N + j];
    out_yout[j] = tanhf(s + input[j]);
}

// ---------------------------------------------------------------------------
// Kernel 3: hebb' = (1-eta)*hebb + eta*yin[i]*yout[j]. Pure streaming,
// float4 vectorized. hebb should be substantially L2-resident from kernel 1.
// ---------------------------------------------------------------------------
__global__ void __launch_bounds__(256) k_hebb_update(
    const float* __restrict__ hebb,
    const float* __restrict__ yin,
    const float* __restrict__ yout,   // = d_out
    const float* __restrict__ eta,
    float* __restrict__ out_hebb)     // = d_out + N
{
    const size_t t   = (size_t)blockIdx.x * blockDim.x + threadIdx.x;
    const size_t idx = t * 4;                 // element index in N*N
    const int i = (int)(idx >> 12);           // row (N = 2^12)
    const int j = (int)(idx & (N - 1));       // col (vec4 never crosses a row)

    const float e   = eta[0];
    const float ome = 1.f - e;
    const float yie = yin[i] * e;             // broadcast within warp

    const float4 h  = *reinterpret_cast<const float4*>(hebb + idx);
    const float4 yo = *reinterpret_cast<const float4*>(yout + j);

    float4 r;
    r.x = fmaf(ome, h.x, yie * yo.x);
    r.y = fmaf(ome, h.y, yie * yo.y);
    r.z = fmaf(ome, h.z, yie * yo.z);
    r.w = fmaf(ome, h.w, yie * yo.w);

    *reinterpret_cast<float4*>(out_hebb + idx) = r;
}

extern "C" void kernel_launch(void* const* d_in, const int* in_sizes, int n_in,
                              void* d_out, int out_size)
{
    const float* input = (const float*)d_in[0];
    const float* yin   = (const float*)d_in[1];
    const float* hebb  = (const float*)d_in[2];
    const float* w     = (const float*)d_in[3];
    const float* alpha = (const float*)d_in[4];
    const float* eta   = (const float*)d_in[5];

    float* out      = (float*)d_out;
    float* out_yout = out;
    float* out_hebb = out + N;

    // 1) split-K matvec partials
    dim3 g1(COL_BLOCKS, SPLITS);
    k_matvec_partial<<<g1, MV_THREADS>>>(yin, w, alpha, hebb);

    // 2) reduce + tanh -> yout
    k_reduce_tanh<<<(N + 255) / 256, 256>>>(input, out_yout);

    // 3) hebb update (16M elems / 4 per thread / 256 per block = 16384 blocks)
    const int hb_blocks = (N * N) / (4 * 256);
    k_hebb_update<<<hb_blocks, 256>>>(hebb, yin, out_yout, eta, out_hebb);
}

// round 2
// speedup vs baseline: 1.1501x; 1.1501x over previous
#include <cuda_runtime.h>
#include <math.h>

// Problem: N = 4096
//   yout = tanh(yin @ (w + alpha*hebb) + input)            [1, N]
//   hebb' = (1-eta)*hebb + eta * outer(yin, yout)          [N, N]
// Inputs: input[N], yin[N], hebb[N*N], w[N*N], alpha[N*N], eta[1]
// Output: d_out = [ yout (N floats) | hebb_new (N*N floats) ]

#define N 4096
#define SPLITS 256             // row splits for the matvec (split-K)
#define ROWS_PER (N / SPLITS)  // 16 rows per split
#define MV_THREADS 256         // each thread owns 4 columns -> 1024 cols/block
#define COL_BLOCKS (N / (MV_THREADS * 4))  // 4

// Deterministic scratch for split-K partial sums (4 MB). No atomics ->
// bit-identical results every replay.
__device__ float g_partial[SPLITS * N];

// ---------------------------------------------------------------------------
// Kernel 1: partial matvec. 1024 CTAs for latency hiding.
// w/alpha are streamed with evict-first (__ldcs) so hebb stays L2-resident
// for kernel 3. hebb uses the default (cache-all) policy.
// ---------------------------------------------------------------------------
__global__ void __launch_bounds__(MV_THREADS) k_matvec_partial(
    const float* __restrict__ yin,
    const float* __restrict__ w,
    const float* __restrict__ alpha,
    const float* __restrict__ hebb)
{
    const int j  = blockIdx.x * (MV_THREADS * 4) + threadIdx.x * 4;
    const int r0 = blockIdx.y * ROWS_PER;

    float4 acc = make_float4(0.f, 0.f, 0.f, 0.f);

    const float4* __restrict__ wp = reinterpret_cast<const float4*>(w     + (size_t)r0 * N + j);
    const float4* __restrict__ ap = reinterpret_cast<const float4*>(alpha + (size_t)r0 * N + j);
    const float4* __restrict__ hp = reinterpret_cast<const float4*>(hebb  + (size_t)r0 * N + j);
    const int stride4 = N / 4;

    #pragma unroll
    for (int i = 0; i < ROWS_PER; ++i) {
        const float  y  = __ldg(&yin[r0 + i]);
        const float4 w4 = __ldcs(wp);   // evict-first: don't pollute L2
        const float4 a4 = __ldcs(ap);   // evict-first
        const float4 h4 = __ldg(hp);    // keep hebb in L2 for kernel 3
        acc.x = fmaf(y, fmaf(a4.x, h4.x, w4.x), acc.x);
        acc.y = fmaf(y, fmaf(a4.y, h4.y, w4.y), acc.y);
        acc.z = fmaf(y, fmaf(a4.z, h4.z, w4.z), acc.z);
        acc.w = fmaf(y, fmaf(a4.w, h4.w, w4.w), acc.w);
        wp += stride4; ap += stride4; hp += stride4;
    }

    *reinterpret_cast<float4*>(&g_partial[(size_t)blockIdx.y * N + j]) = acc;
}

// ---------------------------------------------------------------------------
// Kernel 2: reduce the SPLITS partials, add input, tanh, write yout.
// ---------------------------------------------------------------------------
__global__ void k_reduce_tanh(const float* __restrict__ input,
                              float* __restrict__ out_yout)
{
    const int j = blockIdx.x * blockDim.x + threadIdx.x;
    if (j >= N) return;
    float s = 0.f;
    #pragma unroll 16
    for (int p = 0; p < SPLITS; ++p)
        s += g_partial[(size_t)p * N + j];
    out_yout[j] = tanhf(s + input[j]);
}

// ---------------------------------------------------------------------------
// Kernel 3: hebb' = (1-eta)*hebb + eta*yin[i]*yout[j].
// hebb read should hit L2 (preserved by k1's streaming hints); output is
// written evict-first so the stores don't flush L2.
// ---------------------------------------------------------------------------
__global__ void __launch_bounds__(256) k_hebb_update(
    const float* __restrict__ hebb,
    const float* __restrict__ yin,
    const float* __restrict__ yout,   // = d_out
    const float* __restrict__ eta,
    float* __restrict__ out_hebb)     // = d_out + N
{
    const size_t t   = (size_t)blockIdx.x * blockDim.x + threadIdx.x;
    const size_t idx = t * 4;                 // element index in N*N
    const int i = (int)(idx >> 12);           // row (N = 2^12)
    const int j = (int)(idx & (N - 1));       // col (vec4 never crosses a row)

    const float e   = eta[0];
    const float ome = 1.f - e;
    const float yie = yin[i] * e;             // warp-uniform broadcast

    const float4 h  = __ldg(reinterpret_cast<const float4*>(hebb + idx));
    const float4 yo = __ldg(reinterpret_cast<const float4*>(yout + j));

    float4 r;
    r.x = fmaf(ome, h.x, yie * yo.x);
    r.y = fmaf(ome, h.y, yie * yo.y);
    r.z = fmaf(ome, h.z, yie * yo.z);
    r.w = fmaf(ome, h.w, yie * yo.w);

    __stcs(reinterpret_cast<float4*>(out_hebb + idx), r);
}

extern "C" void kernel_launch(void* const* d_in, const int* in_sizes, int n_in,
                              void* d_out, int out_size)
{
    const float* input = (const float*)d_in[0];
    const float* yin   = (const float*)d_in[1];
    const float* hebb  = (const float*)d_in[2];
    const float* w     = (const float*)d_in[3];
    const float* alpha = (const float*)d_in[4];
    const float* eta   = (const float*)d_in[5];

    float* out      = (float*)d_out;
    float* out_yout = out;
    float* out_hebb = out + N;

    // 1) split-K matvec partials: 4 x 256 = 1024 CTAs
    dim3 g1(COL_BLOCKS, SPLITS);
    k_matvec_partial<<<g1, MV_THREADS>>>(yin, w, alpha, hebb);

    // 2) reduce + tanh -> yout
    k_reduce_tanh<<<(N + 255) / 256, 256>>>(input, out_yout);

    // 3) hebb update
    const int hb_blocks = (N * N) / (4 * 256);
    k_hebb_update<<<hb_blocks, 256>>>(hebb, yin, out_yout, eta, out_hebb);
}